// round 11
// baseline (speedup 1.0000x reference)
#include <cuda_runtime.h>
#include <math.h>

// Problem constants (fixed by dataset)
#define NXD   512          // design points
#define MDIM  514          // number of basis functions = NXD + 2 (k=3)
#define NEV   8192         // eval bins
#define NROWS 256          // 8*32 rows
#define SREG  1e-3

#define W     48           // inverse-band half-width used for truncation
#define D     56           // per-column inverse computation window
#define PB    100          // taps per M row: p in [max(0,j-51), j+48]

// ---------------------------------------------------------------------------
// Compile-time: M = A^-1(banded) * B^T, the full fit operator.
// coef[j] = sum_t M[j][t] * z[pstart(j)+t],  pstart(j) = max(0, j-51)
// ---------------------------------------------------------------------------
struct MBTab { float mb[MDIM][PB]; };

constexpr double cx(int i) { return -1.0 + 2.0 * (double)i / 511.0; }
constexpr double cknot(int i) {
    int j = i - 3;
    if (j < 0) j = 0;
    if (j > 511) j = 511;
    return cx(j);
}
constexpr double csqrt(double v) {
    double g = v < 1.0 ? 1.0 : v;
    for (int it = 0; it < 40; ++it) g = 0.5 * (g + v / g);
    return g;
}

constexpr MBTab make_mb() {
    MBTab T{};
    double dwd[NXD][4] = {};
    for (int p = 0; p < NXD; ++p) {
        int base = p < 510 ? p : 510;
        int i = base + 3;
        double x = cx(p);
        double N[4] = {1, 0, 0, 0};
        double left[4] = {}, right[4] = {};
        for (int j = 1; j <= 3; ++j) {
            left[j]  = x - cknot(i + 1 - j);
            right[j] = cknot(i + j) - x;
            double saved = 0;
            for (int r = 0; r < j; ++r) {
                double temp = N[r] / (right[r + 1] + left[j - r]);
                N[r]  = saved + right[r + 1] * temp;
                saved = left[j - r] * temp;
            }
            N[j] = saved;
        }
        for (int a = 0; a < 4; ++a) dwd[p][a] = N[a];
    }
    double band[4][MDIM] = {};
    for (int p = 0; p < NXD; ++p) {
        int base = p < 510 ? p : 510;
        for (int a = 0; a < 4; ++a)
            for (int b = a; b < 4; ++b)
                band[b - a][base + a] += dwd[p][a] * dwd[p][b];
    }
    for (int r = 0; r < MDIM; ++r) band[0][r] += SREG;
    double Ld[MDIM] = {}, L1a[MDIM] = {}, L2a[MDIM] = {}, L3a[MDIM] = {};
    for (int i = 0; i < MDIM; ++i) {
        double l3 = 0, l2 = 0, l1 = 0;
        if (i >= 3) l3 = band[3][i - 3] / Ld[i - 3];
        if (i >= 2) {
            double s = band[2][i - 2];
            if (i >= 3) s -= l3 * L1a[i - 2];
            l2 = s / Ld[i - 2];
        }
        if (i >= 1) {
            double s = band[1][i - 1];
            if (i >= 2) s -= l2 * L1a[i - 1];
            if (i >= 3) s -= l3 * L2a[i - 1];
            l1 = s / Ld[i - 1];
        }
        double s = band[0][i] - l1 * l1 - l2 * l2 - l3 * l3;
        Ld[i] = csqrt(s);
        L1a[i] = l1; L2a[i] = l2; L3a[i] = l3;
    }
    for (int j = 0; j < MDIM; ++j) {
        double yw[D + 1] = {};
        yw[0] = 1.0 / Ld[j];
        for (int d = 1; d <= D; ++d) {
            int jj = j + d;
            if (jj < MDIM) {
                double s = -(L1a[jj] * yw[d - 1]);
                if (d >= 2) s -= L2a[jj] * yw[d - 2];
                if (d >= 3) s -= L3a[jj] * yw[d - 3];
                yw[d] = s / Ld[jj];
            }
        }
        double cw[2 * D + 4] = {};
        for (int s = 2 * D; s >= 0; --s) {
            int jj = j - D + s;
            if (jj >= 0 && jj < MDIM) {
                double yv = (s >= D) ? yw[s - D] : 0.0;
                double c = yv;
                c -= (jj + 1 < MDIM ? L1a[jj + 1] : 0.0) * cw[s + 1];
                c -= (jj + 2 < MDIM ? L2a[jj + 2] : 0.0) * cw[s + 2];
                c -= (jj + 3 < MDIM ? L3a[jj + 3] : 0.0) * cw[s + 3];
                cw[s] = c / Ld[jj];
            }
        }
        int ps = j - 51; if (ps < 0) ps = 0;
        int pe = j + W;  if (pe > 511) pe = 511;
        for (int t = 0; t < PB; ++t) {
            int p = ps + t;
            double sum = 0.0;
            if (p <= pe) {
                int base = p < 510 ? p : 510;
                for (int a = 0; a < 4; ++a) {
                    int jj = base + a;
                    int s = jj - (j - D);
                    if (s >= 0 && s <= 2 * D) sum += dwd[p][a] * cw[s];
                }
            }
            T.mb[j][t] = (float)sum;
        }
    }
    return T;
}

__device__ const MBTab g_mb = make_mb();

// ---------------------------------------------------------------------------
// Fused kernel. grid (64 e-chunks of 128, 16 r-chunks of 16), 256 threads.
// ---------------------------------------------------------------------------
#define EPB   128
#define RPB   16
#define JWIN  13           // j-window
#define JS    13           // s_coef row stride
#define PW    112          // re-origined M width (12 + 100)
#define NCH   (PW / 4)     // 28 float4 chunks
#define ZS    116          // z row stride in floats (29 chunks; gcd(29,32)=1)

__device__ __forceinline__ float kf(int i) {
    int j = i - 3;
    j = j < 0 ? 0 : (j > 511 ? 511 : j);
    return (float)(-1.0 + 2.0 * (double)j / 511.0);
}

__device__ __forceinline__ int ebase_of(int e) {
    double x = -1.0 + 2.0 * (double)e / 8191.0;
    float xf = (float)x;
    int id = (int)floor(((double)xf + 1.0) * 255.5);
    return id < 0 ? 0 : (id > 510 ? 510 : id);
}

// general fp32 De Boor (boundary intervals only)
__device__ __forceinline__ void ewts(int e, float4& wout, int& idx) {
    float x = (float)(-1.0 + 2.0 * (double)e / 8191.0);
    int id = ebase_of(e);
    int i = id + 3;
    float N[4] = {1.f, 0.f, 0.f, 0.f};
    float left[4], right[4];
#pragma unroll
    for (int j = 1; j <= 3; ++j) {
        left[j]  = x - kf(i + 1 - j);
        right[j] = kf(i + j) - x;
        float saved = 0.f;
#pragma unroll
        for (int r = 0; r < 3; ++r) {
            if (r < j) {
                float temp = __fdividef(N[r], right[r + 1] + left[j - r]);
                N[r]  = fmaf(right[r + 1], temp, saved);
                saved = left[j - r] * temp;
            }
        }
        N[j] = saved;
    }
    idx = id;
    wout = make_float4(N[0], N[1], N[2], N[3]);
}

__device__ __forceinline__ void weights(int e, float4& w, int& idx) {
    int prod = e * 511;
    int id = prod / 8191;
    if (id > 510) id = 510;
    if (id >= 3 && id <= 507) {
        float u = (float)(prod - id * 8191) * (1.0f / 8191.0f);
        float um = 1.f - u;
        float u2 = u * u, um2 = um * um;
        w.x = um2 * um * (1.f / 6.f);
        w.w = u2 * u * (1.f / 6.f);
        w.y = fmaf(3.f * u, u2, fmaf(-6.f, u2, 4.f)) * (1.f / 6.f);
        w.z = 1.f - w.x - w.y - w.w;
        idx = id;
    } else {
        ewts(e, w, idx);
    }
}

__device__ __forceinline__ float ev5(float4 w, int o,
                                     float c0, float c1, float c2,
                                     float c3, float c4) {
    float a0 = o ? c1 : c0;
    float a1 = o ? c2 : c1;
    float a2 = o ? c3 : c2;
    float a3 = o ? c4 : c3;
    float v = w.x * a0;
    v = fmaf(w.y, a1, v);
    v = fmaf(w.z, a2, v);
    v = fmaf(w.w, a3, v);
    return v;
}

__global__ void __launch_bounds__(256, 6) kfused(const float* __restrict__ Z,
                                                 float* __restrict__ out) {
    __shared__ float s_z[RPB * ZS];       // Z window [pbase, pbase+PW)
    __shared__ float s_m[JWIN][PW];       // fit operator, re-origined to pbase
    __shared__ float s_coef[RPB][JS];
    int tid = threadIdx.x;
    int e0 = blockIdx.x * EPB;
    int rbase = blockIdx.y * RPB;

    int j0a = ebase_of(e0);
    int j0b = e0 * 511 / 8191; if (j0b > 510) j0b = 510;
    int j0 = j0a < j0b ? j0a : j0b;
    int pbase = j0 - 51; if (pbase < 0) pbase = 0;

    // stage Z window (coalesced: consecutive p per row)
    for (int idx = tid; idx < RPB * PW; idx += 256) {
        int r = idx / PW, pp = idx - r * PW;
        int p = pbase + pp;
        s_z[r * ZS + pp] = (p < NXD) ? Z[(size_t)(rbase + r) * NXD + p] : 0.f;
    }
    // stage M tile, re-origined: s_m[jl][t] = M[j][p=pbase+t]
    for (int idx = tid; idx < JWIN * PW; idx += 256) {
        int jl = idx / PW, t = idx - jl * PW;
        int j = j0 + jl;
        float v = 0.f;
        if (j < MDIM) {
            int ps = j - 51; if (ps < 0) ps = 0;
            int tg = pbase + t - ps;
            if (tg >= 0 && tg < PB) v = g_mb.mb[j][tg];
        }
        s_m[jl][t] = v;
    }
    __syncthreads();

    // coef: warp w in 0..6, lanes = 16 r x 2 j (lane>>4). z 2-way multicast,
    // M 2 addresses per warp.
    {
        int lane = tid & 31;
        int wp = tid >> 5;
        int r = lane & 15;
        int jl = wp * 2 + (lane >> 4);
        if (wp < 7 && jl < JWIN) {
            const float4* zr = (const float4*)(s_z + r * ZS);
            const float4* mr = (const float4*)s_m[jl];
            float a0 = 0.f;
#pragma unroll 7
            for (int t = 0; t < NCH; ++t) {
                float4 z = zr[t];
                float4 m = mr[t];
                a0 = fmaf(m.x, z.x, a0); a0 = fmaf(m.y, z.y, a0);
                a0 = fmaf(m.z, z.z, a0); a0 = fmaf(m.w, z.w, a0);
            }
            s_coef[r][jl] = a0;
        }
    }
    __syncthreads();

    // eval: 64 e-groups (2 e each) x 4 row-groups (4 rows each).
    // Within a warp all lanes share the row-group -> s_coef reads broadcast.
    int eg = tid & 63;
    int rg = tid >> 6;
    int e = e0 + eg * 2;
    float4 w0, w1;
    int i0, i1;
    weights(e,     w0, i0);
    weights(e + 1, w1, i1);
    int b0 = i0 - j0;
    int o1 = i1 - i0;

    float2* outv = (float2*)(out + e);
#pragma unroll
    for (int rr = 0; rr < 4; ++rr) {
        int rl = rg * 4 + rr;
        int row = rbase + rl;
        const float* cr = &s_coef[rl][b0];
        float c0 = cr[0], c1 = cr[1], c2 = cr[2], c3 = cr[3], c4 = cr[4];
        float2 v;
        v.x = w0.x * c0;
        v.x = fmaf(w0.y, c1, v.x);
        v.x = fmaf(w0.z, c2, v.x);
        v.x = fmaf(w0.w, c3, v.x);
        v.y = ev5(w1, o1, c0, c1, c2, c3, c4);
        outv[(size_t)row * (NEV / 2)] = v;
    }
}

// ---------------------------------------------------------------------------
extern "C" void kernel_launch(void* const* d_in, const int* in_sizes, int n_in,
                              void* d_out, int out_size) {
    const float* Z = (const float*)d_in[0];
    float* out = (float*)d_out;
    kfused<<<dim3(NEV / EPB, NROWS / RPB), 256>>>(Z, out);
}

// round 12
// speedup vs baseline: 1.3029x; 1.3029x over previous
#include <cuda_runtime.h>
#include <math.h>

// Problem constants (fixed by dataset)
#define NXD   512          // design points
#define MDIM  514          // number of basis functions = NXD + 2 (k=3)
#define NEV   8192         // eval bins
#define NROWS 256          // 8*32 rows
#define SREG  1e-3

#define W     48           // inverse-band half-width used for truncation
#define D     56           // per-column inverse computation window
#define PB    100          // taps per M row: p in [max(0,j-51), j+48]

// ---------------------------------------------------------------------------
// Compile-time: M = A^-1(banded) * B^T, the full fit operator.
// ---------------------------------------------------------------------------
struct MBTab { float mb[MDIM][PB]; };

constexpr double cx(int i) { return -1.0 + 2.0 * (double)i / 511.0; }
constexpr double cknot(int i) {
    int j = i - 3;
    if (j < 0) j = 0;
    if (j > 511) j = 511;
    return cx(j);
}
constexpr double csqrt(double v) {
    double g = v < 1.0 ? 1.0 : v;
    for (int it = 0; it < 40; ++it) g = 0.5 * (g + v / g);
    return g;
}

constexpr MBTab make_mb() {
    MBTab T{};
    double dwd[NXD][4] = {};
    for (int p = 0; p < NXD; ++p) {
        int base = p < 510 ? p : 510;
        int i = base + 3;
        double x = cx(p);
        double N[4] = {1, 0, 0, 0};
        double left[4] = {}, right[4] = {};
        for (int j = 1; j <= 3; ++j) {
            left[j]  = x - cknot(i + 1 - j);
            right[j] = cknot(i + j) - x;
            double saved = 0;
            for (int r = 0; r < j; ++r) {
                double temp = N[r] / (right[r + 1] + left[j - r]);
                N[r]  = saved + right[r + 1] * temp;
                saved = left[j - r] * temp;
            }
            N[j] = saved;
        }
        for (int a = 0; a < 4; ++a) dwd[p][a] = N[a];
    }
    double band[4][MDIM] = {};
    for (int p = 0; p < NXD; ++p) {
        int base = p < 510 ? p : 510;
        for (int a = 0; a < 4; ++a)
            for (int b = a; b < 4; ++b)
                band[b - a][base + a] += dwd[p][a] * dwd[p][b];
    }
    for (int r = 0; r < MDIM; ++r) band[0][r] += SREG;
    double Ld[MDIM] = {}, L1a[MDIM] = {}, L2a[MDIM] = {}, L3a[MDIM] = {};
    for (int i = 0; i < MDIM; ++i) {
        double l3 = 0, l2 = 0, l1 = 0;
        if (i >= 3) l3 = band[3][i - 3] / Ld[i - 3];
        if (i >= 2) {
            double s = band[2][i - 2];
            if (i >= 3) s -= l3 * L1a[i - 2];
            l2 = s / Ld[i - 2];
        }
        if (i >= 1) {
            double s = band[1][i - 1];
            if (i >= 2) s -= l2 * L1a[i - 1];
            if (i >= 3) s -= l3 * L2a[i - 1];
            l1 = s / Ld[i - 1];
        }
        double s = band[0][i] - l1 * l1 - l2 * l2 - l3 * l3;
        Ld[i] = csqrt(s);
        L1a[i] = l1; L2a[i] = l2; L3a[i] = l3;
    }
    for (int j = 0; j < MDIM; ++j) {
        double yw[D + 1] = {};
        yw[0] = 1.0 / Ld[j];
        for (int d = 1; d <= D; ++d) {
            int jj = j + d;
            if (jj < MDIM) {
                double s = -(L1a[jj] * yw[d - 1]);
                if (d >= 2) s -= L2a[jj] * yw[d - 2];
                if (d >= 3) s -= L3a[jj] * yw[d - 3];
                yw[d] = s / Ld[jj];
            }
        }
        double cw[2 * D + 4] = {};
        for (int s = 2 * D; s >= 0; --s) {
            int jj = j - D + s;
            if (jj >= 0 && jj < MDIM) {
                double yv = (s >= D) ? yw[s - D] : 0.0;
                double c = yv;
                c -= (jj + 1 < MDIM ? L1a[jj + 1] : 0.0) * cw[s + 1];
                c -= (jj + 2 < MDIM ? L2a[jj + 2] : 0.0) * cw[s + 2];
                c -= (jj + 3 < MDIM ? L3a[jj + 3] : 0.0) * cw[s + 3];
                cw[s] = c / Ld[jj];
            }
        }
        int ps = j - 51; if (ps < 0) ps = 0;
        int pe = j + W;  if (pe > 511) pe = 511;
        for (int t = 0; t < PB; ++t) {
            int p = ps + t;
            double sum = 0.0;
            if (p <= pe) {
                int base = p < 510 ? p : 510;
                for (int a = 0; a < 4; ++a) {
                    int jj = base + a;
                    int s = jj - (j - D);
                    if (s >= 0 && s <= 2 * D) sum += dwd[p][a] * cw[s];
                }
            }
            T.mb[j][t] = (float)sum;
        }
    }
    return T;
}

__device__ const MBTab g_mb = make_mb();

// ---------------------------------------------------------------------------
// Compile-time eval tables: weights (float4) + base index per eval point.
// Single convention: b[e] = floor(e*511/8191), clamped; De Boor in double.
// ---------------------------------------------------------------------------
struct EvTab {
    float w[NEV][4];
    int   b[NEV];
};

constexpr EvTab make_ev() {
    EvTab T{};
    for (int e = 0; e < NEV; ++e) {
        int id = (e * 511) / 8191;
        if (id > 510) id = 510;
        double x = -1.0 + 2.0 * (double)e / 8191.0;
        int i = id + 3;
        double N[4] = {1, 0, 0, 0};
        double left[4] = {}, right[4] = {};
        for (int j = 1; j <= 3; ++j) {
            left[j]  = x - cknot(i + 1 - j);
            right[j] = cknot(i + j) - x;
            double saved = 0;
            for (int r = 0; r < j; ++r) {
                double temp = N[r] / (right[r + 1] + left[j - r]);
                N[r]  = saved + right[r + 1] * temp;
                saved = left[j - r] * temp;
            }
            N[j] = saved;
        }
        for (int a = 0; a < 4; ++a) T.w[e][a] = (float)N[a];
        T.b[e] = id;
    }
    return T;
}

__device__ const EvTab g_ev = make_ev();

// ---------------------------------------------------------------------------
// Fused kernel. grid (64 e-chunks of 128, 8 r-chunks of 32), 256 threads.
// ---------------------------------------------------------------------------
#define EPB   128
#define RPB   32
#define JWIN  13           // j-window (max b-span 9 + 3)
#define JS    13           // s_coef row stride
#define PW    112          // re-origined M width (12 + 100)
#define NCH   (PW / 4)     // 28 float4 chunks
#define ZS    116          // z row stride in floats (29 chunks; gcd(29,32)=1)

__device__ __forceinline__ float ev5(const float* w, int o,
                                     float c0, float c1, float c2,
                                     float c3, float c4) {
    float a0 = o ? c1 : c0;
    float a1 = o ? c2 : c1;
    float a2 = o ? c3 : c2;
    float a3 = o ? c4 : c3;
    float v = w[0] * a0;
    v = fmaf(w[1], a1, v);
    v = fmaf(w[2], a2, v);
    v = fmaf(w[3], a3, v);
    return v;
}

__global__ void __launch_bounds__(256, 5) kfused(const float* __restrict__ Z,
                                                 float* __restrict__ out) {
    __shared__ float s_z[RPB * ZS];       // Z window [pbase, pbase+PW)
    __shared__ float s_m[JWIN][PW];       // fit operator, re-origined to pbase
    __shared__ float s_coef[RPB][JS];
    int tid = threadIdx.x;
    int e0 = blockIdx.x * EPB;
    int rbase = blockIdx.y * RPB;

    int j0 = g_ev.b[e0];                  // broadcast LDG
    int pbase = j0 - 51; if (pbase < 0) pbase = 0;

    // stage Z window (coalesced: consecutive p per row)
    for (int idx = tid; idx < RPB * PW; idx += 256) {
        int r = idx / PW, pp = idx - r * PW;
        int p = pbase + pp;
        s_z[r * ZS + pp] = (p < NXD) ? Z[(size_t)(rbase + r) * NXD + p] : 0.f;
    }
    // stage M tile, re-origined: s_m[jl][t] = M[j][p=pbase+t]
    for (int idx = tid; idx < JWIN * PW; idx += 256) {
        int jl = idx / PW, t = idx - jl * PW;
        int j = j0 + jl;
        float v = 0.f;
        if (j < MDIM) {
            int ps = j - 51; if (ps < 0) ps = 0;
            int tg = pbase + t - ps;
            if (tg >= 0 && tg < PB) v = g_mb.mb[j][tg];
        }
        s_m[jl][t] = v;
    }
    __syncthreads();

    // coef: warps 0-3 handle 3 j each (broadcast M, z reused 3x); warp 4: 1 j.
    {
        int r = tid & 31;
        int wp = tid >> 5;
        const float4* zr = (const float4*)(s_z + r * ZS);
        if (wp < 4) {
            int jl = wp * 3;
            const float4* m0 = (const float4*)s_m[jl + 0];
            const float4* m1 = (const float4*)s_m[jl + 1];
            const float4* m2 = (const float4*)s_m[jl + 2];
            float a0 = 0.f, a1 = 0.f, a2 = 0.f;
#pragma unroll 7
            for (int t = 0; t < NCH; ++t) {
                float4 z = zr[t];
                float4 ma = m0[t];
                a0 = fmaf(ma.x, z.x, a0); a0 = fmaf(ma.y, z.y, a0);
                a0 = fmaf(ma.z, z.z, a0); a0 = fmaf(ma.w, z.w, a0);
                float4 mb = m1[t];
                a1 = fmaf(mb.x, z.x, a1); a1 = fmaf(mb.y, z.y, a1);
                a1 = fmaf(mb.z, z.z, a1); a1 = fmaf(mb.w, z.w, a1);
                float4 mc = m2[t];
                a2 = fmaf(mc.x, z.x, a2); a2 = fmaf(mc.y, z.y, a2);
                a2 = fmaf(mc.z, z.z, a2); a2 = fmaf(mc.w, z.w, a2);
            }
            s_coef[r][jl + 0] = a0;
            s_coef[r][jl + 1] = a1;
            s_coef[r][jl + 2] = a2;
        } else if (wp == 4) {
            const float4* m0 = (const float4*)s_m[12];
            float a0 = 0.f;
#pragma unroll 7
            for (int t = 0; t < NCH; ++t) {
                float4 z = zr[t];
                float4 ma = m0[t];
                a0 = fmaf(ma.x, z.x, a0); a0 = fmaf(ma.y, z.y, a0);
                a0 = fmaf(ma.z, z.z, a0); a0 = fmaf(ma.w, z.w, a0);
            }
            s_coef[r][12] = a0;
        }
    }
    __syncthreads();

    // eval: lanes = 32 e-groups (4 e each, coalesced 64B weight loads),
    // warps = 8 row-groups (4 rows each); s_coef reads broadcast per warp.
    int eg = tid & 31;
    int rg = tid >> 5;
    int e = e0 + eg * 4;

    const float4* wt = (const float4*)g_ev.w[e];   // 64B contiguous per thread
    float4 w0 = wt[0], w1 = wt[1], w2 = wt[2], w3 = wt[3];
    int4 bi = *(const int4*)&g_ev.b[e];            // 16B contiguous per thread
    int b0 = bi.x - j0;
    int o1 = bi.y - bi.x, o2 = bi.z - bi.x, o3 = bi.w - bi.x;

    float4* outv = (float4*)(out + e);
#pragma unroll
    for (int rr = 0; rr < 4; ++rr) {
        int rl = rg * 4 + rr;
        int row = rbase + rl;
        const float* cr = &s_coef[rl][b0];
        float c0 = cr[0], c1 = cr[1], c2 = cr[2], c3 = cr[3], c4 = cr[4];
        float4 v;
        v.x = w0.x * c0;
        v.x = fmaf(w0.y, c1, v.x);
        v.x = fmaf(w0.z, c2, v.x);
        v.x = fmaf(w0.w, c3, v.x);
        v.y = ev5((const float*)&w1, o1, c0, c1, c2, c3, c4);
        v.z = ev5((const float*)&w2, o2, c0, c1, c2, c3, c4);
        v.w = ev5((const float*)&w3, o3, c0, c1, c2, c3, c4);
        outv[(size_t)row * (NEV / 4)] = v;
    }
}

// ---------------------------------------------------------------------------
extern "C" void kernel_launch(void* const* d_in, const int* in_sizes, int n_in,
                              void* d_out, int out_size) {
    const float* Z = (const float*)d_in[0];
    float* out = (float*)d_out;
    kfused<<<dim3(NEV / EPB, NROWS / RPB), 256>>>(Z, out);
}